// round 9
// baseline (speedup 1.0000x reference)
#include <cuda_runtime.h>

// Discriminator neural-SDE scan. B=512, T=4096, D=8, H=16, W=16.
// ONE warp per batch element (512 x 32). ZERO SMEM / ZERO barriers in loop:
//   all state register-resident, exchanged via pipelined SHFL.
//   P1: lane -> hidden row (0-15 vW1, 16-31 cW1); y gathered as 8 packed
//       pairs via 16 shfls; packed fma2 dot; lipswish.
//   P2: hc gathered as 8 packed pairs (16 shfls); 4 g-rows/lane as packed
//       dots; f row hidx K-split (8 shfls + 8 FMA + xor); einsum d-quad +
//       xor; ynew = ylane + fv + part computed redundantly in BOTH lanes of
//       the pair (fv, part are pair-symmetric) -> y register-resident.
// EX2/RCP-based activations (accuracy-safe).

#define T_STEPS 4096
#define FULLMASK 0xffffffffu
typedef unsigned long long ull;

__device__ __forceinline__ ull fma2(ull a, ull b, ull c) {
    ull r; asm("fma.rn.f32x2 %0, %1, %2, %3;" : "=l"(r) : "l"(a), "l"(b), "l"(c)); return r;
}
__device__ __forceinline__ ull pack2(float x, float y) {
    ull r; asm("mov.b64 %0, {%1,%2};" : "=l"(r) : "f"(x), "f"(y)); return r;
}
__device__ __forceinline__ float2 unpack2(ull v) {
    float2 r; asm("mov.b64 {%0,%1}, %2;" : "=f"(r.x), "=f"(r.y) : "l"(v)); return r;
}

// tanh(x) = 1 - 2/(exp(2x)+1); EX2-based, branchless, saturates via inf/0.
__device__ __forceinline__ float tanh_fast(float x) {
    float e = __expf(2.f * x);
    return 1.f - __fdividef(2.f, e + 1.f);
}
// lipswish(x) = 0.909 * x * sigmoid(x), EX2-based.
__device__ __forceinline__ float lipswish_fast(float x) {
    float ax = 0.909f * x;
    return ax * __fdividef(1.f, 1.f + __expf(-x));
}

__global__ void __launch_bounds__(32) sde_scan_kernel(
    const float* __restrict__ ts, const float* __restrict__ ys,
    const float* __restrict__ iW1, const float* __restrict__ ib1,
    const float* __restrict__ iW2, const float* __restrict__ ib2,
    const float* __restrict__ vW1, const float* __restrict__ vb1,
    const float* __restrict__ vW2, const float* __restrict__ vb2,
    const float* __restrict__ cW1, const float* __restrict__ cb1,
    const float* __restrict__ cW2, const float* __restrict__ cb2,
    const float* __restrict__ rW, const float* __restrict__ rb,
    float* __restrict__ out)
{
    const int b    = blockIdx.x;
    const int lane = threadIdx.x & 31;

    const float t0 = ts[0];
    const float* __restrict__ ysb = ys + (size_t)b * (T_STEPS * 8);

    const int hidx  = lane >> 1;      // h for g rows, f row, y slot
    const int khalf = lane & 1;

    // ---- P1 weights: row = lane; [t-coef | 16 y-coefs] packed as 8 pairs ----
    ull w1p[8]; float w1t, b1r;
    {
        const float* W = (lane < 16) ? (vW1 + lane * 17) : (cW1 + (lane - 16) * 17);
        w1t = W[0];
#pragma unroll
        for (int q = 0; q < 8; q++) w1p[q] = pack2(W[1 + 2 * q], W[2 + 2 * q]);
        b1r = (lane < 16) ? vb1[lane] : cb1[lane - 16];
    }

    // ---- g packed weights: rows 4l..4l+3, columns as pairs ----
    ull cwA[8], cwB[8], cwC[8], cwD[8];
    float cbr0, cbr1, cbr2, cbr3;
    {
        const int fl = 4 * lane;
        const float* Wa = cW2 + (fl + 0) * 16;
        const float* Wb = cW2 + (fl + 1) * 16;
        const float* Wc = cW2 + (fl + 2) * 16;
        const float* Wd = cW2 + (fl + 3) * 16;
#pragma unroll
        for (int q = 0; q < 8; q++) {
            cwA[q] = pack2(Wa[2 * q], Wa[2 * q + 1]);
            cwB[q] = pack2(Wb[2 * q], Wb[2 * q + 1]);
            cwC[q] = pack2(Wc[2 * q], Wc[2 * q + 1]);
            cwD[q] = pack2(Wd[2 * q], Wd[2 * q + 1]);
        }
        cbr0 = cb2[fl]; cbr1 = cb2[fl + 1]; cbr2 = cb2[fl + 2]; cbr3 = cb2[fl + 3];
    }

    // ---- f weights: row hidx, K-half khalf ----
    float vfh[8], fbb;
    {
#pragma unroll
        for (int k = 0; k < 8; k++) vfh[k] = vW2[hidx * 16 + khalf * 8 + k];
        fbb = (khalf == 0) ? vb2[hidx] : 0.f;
    }

    // ---- initial MLP: y0 = relu([t0, ys0] @ iW1^T + ib1) @ iW2^T + ib2 ----
    float ynew;   // this lane's y[hidx], register-resident through the scan
    {
        float a = 0.f;
        if (lane < 16) {
            a = fmaf(iW1[lane * 9], t0, ib1[lane]);
#pragma unroll
            for (int k = 0; k < 8; k++) a = fmaf(iW1[lane * 9 + 1 + k], ysb[k], a);
            a = fmaxf(a, 0.f);
        }
        float hv[16];
#pragma unroll
        for (int k = 0; k < 16; k++) hv[k] = __shfl_sync(FULLMASK, a, k);
        float y0 = 0.f;
        if (lane < 16) {
            y0 = ib2[lane];
#pragma unroll
            for (int k = 0; k < 16; k++) y0 = fmaf(iW2[lane * 16 + k], hv[k], y0);
        }
        if (lane == 0) {
            float acc = rb[0];
            // y0 lives in lanes 0-15; gather via shfl below (all lanes exec)
            acc = acc;  // placeholder; real gather after shfls
        }
        float yv16[16];
#pragma unroll
        for (int k = 0; k < 16; k++) yv16[k] = __shfl_sync(FULLMASK, y0, k);
        if (lane == 0) {
            float acc = rb[0];
#pragma unroll
            for (int k = 0; k < 16; k++) acc = fmaf(rW[k], yv16[k], acc);
            out[b * 2 + 0] = acc;
        }
        ynew = __shfl_sync(FULLMASK, y0, hidx);
    }

    // ---- dx: lane tracks d-quad d0 = khalf*4 ----
    const int d0 = khalf * 4;
    auto ldrow = [&](int r) -> float4 {
        return *reinterpret_cast<const float4*>(ysb + (size_t)r * 8 + d0);
    };

    float tf = t0;

    // ---- one Euler step (no barriers, no SMEM) ----
    auto step = [&](const float4 pv, const float4 cv) {
        // dx diffs (off-chain: pv/cv are prefetched registers)
        float dx0 = cv.x - pv.x, dx1 = cv.y - pv.y;
        float dx2 = cv.z - pv.z, dx3 = cv.w - pv.w;

        // ===== P1: gather y pairs, packed dot, lipswish =====
        ull yp[8];
#pragma unroll
        for (int q = 0; q < 8; q++) {
            float ya = __shfl_sync(FULLMASK, ynew, 4 * q);      // y[2q]
            float yb = __shfl_sync(FULLMASK, ynew, 4 * q + 2);  // y[2q+1]
            yp[q] = pack2(ya, yb);
        }
        ull p0 = 0, p1 = 0;
#pragma unroll
        for (int q = 0; q < 8; q += 2) {
            p0 = fma2(w1p[q],     yp[q],     p0);
            p1 = fma2(w1p[q + 1], yp[q + 1], p1);
        }
        float2 u0 = unpack2(p0), u1 = unpack2(p1);
        float pre = ((u0.x + u0.y) + (u1.x + u1.y)) + fmaf(w1t, tf, b1r);
        float h = lipswish_fast(pre);
        tf += 1.f;

        // ===== broadcast h: hc pairs (lanes 16-31), hv K-half (lanes 0-15) =====
        ull hcp[8];
#pragma unroll
        for (int q = 0; q < 8; q++) {
            float ha = __shfl_sync(FULLMASK, h, 16 + 2 * q);
            float hb = __shfl_sync(FULLMASK, h, 17 + 2 * q);
            hcp[q] = pack2(ha, hb);
        }
        float hvv[8];
#pragma unroll
        for (int j = 0; j < 8; j++) hvv[j] = __shfl_sync(FULLMASK, h, khalf * 8 + j);

        // ===== g rows (packed dots, 2 accumulators each) =====
        ull A0 = 0, A1 = 0, B0 = 0, B1 = 0, C0 = 0, C1 = 0, D0 = 0, D1 = 0;
#pragma unroll
        for (int q = 0; q < 8; q += 2) {
            A0 = fma2(cwA[q], hcp[q], A0);  A1 = fma2(cwA[q + 1], hcp[q + 1], A1);
            B0 = fma2(cwB[q], hcp[q], B0);  B1 = fma2(cwB[q + 1], hcp[q + 1], B1);
            C0 = fma2(cwC[q], hcp[q], C0);  C1 = fma2(cwC[q + 1], hcp[q + 1], C1);
            D0 = fma2(cwD[q], hcp[q], D0);  D1 = fma2(cwD[q + 1], hcp[q + 1], D1);
        }
        float2 a0 = unpack2(A0), a1 = unpack2(A1);
        float2 b0 = unpack2(B0), b1 = unpack2(B1);
        float2 c0 = unpack2(C0), c1 = unpack2(C1);
        float2 e0 = unpack2(D0), e1 = unpack2(D1);
        float g0 = tanh_fast(((a0.x + a0.y) + (a1.x + a1.y)) + cbr0);
        float g1 = tanh_fast(((b0.x + b0.y) + (b1.x + b1.y)) + cbr1);
        float g2 = tanh_fast(((c0.x + c0.y) + (c1.x + c1.y)) + cbr2);
        float g3 = tanh_fast(((e0.x + e0.y) + (e1.x + e1.y)) + cbr3);

        // ===== f row hidx (K-split + xor) =====
        float f0 = fbb, f1 = 0.f, f2 = 0.f, f3 = 0.f;
        f0 = fmaf(vfh[0], hvv[0], f0); f1 = fmaf(vfh[1], hvv[1], f1);
        f2 = fmaf(vfh[2], hvv[2], f2); f3 = fmaf(vfh[3], hvv[3], f3);
        f0 = fmaf(vfh[4], hvv[4], f0); f1 = fmaf(vfh[5], hvv[5], f1);
        f2 = fmaf(vfh[6], hvv[6], f2); f3 = fmaf(vfh[7], hvv[7], f3);
        float fp = (f0 + f1) + (f2 + f3);
        fp += __shfl_xor_sync(FULLMASK, fp, 1);
        float fv = tanh_fast(fp);

        // ===== einsum d-quad + pair reduce; redundant pair-symmetric update =====
        float part = g0 * dx0;
        part = fmaf(g1, dx1, part);
        part = fmaf(g2, dx2, part);
        part = fmaf(g3, dx3, part);
        part += __shfl_xor_sync(FULLMASK, part, 1);

        ynew = ynew + fv + part;   // identical in both lanes of the pair
    };

    // ---- main loop: 4-step bodies with register-rotated row prefetch ----
    float4 rA = ldrow(0), rB = ldrow(1), rC = ldrow(2), rD = ldrow(3);
    int n = 0;
#pragma unroll 1
    for (int it = 0; it < 1023; it++) {   // n = 0..4091, prefetch rows n+4..n+7 <= 4095
        float4 q0 = ldrow(n + 4);
        step(rA, rB);
        float4 q1 = ldrow(n + 5);
        step(rB, rC);
        float4 q2 = ldrow(n + 6);
        step(rC, rD);
        float4 q3 = ldrow(n + 7);
        step(rD, q0);
        rA = q0; rB = q1; rC = q2; rD = q3;
        n += 4;
    }
    // tail: n = 4092, 4093, 4094 (rows already resident)
    step(rA, rB);
    step(rB, rC);
    step(rC, rD);

    // ---- readout of yT (gather executed by all lanes) ----
    {
        float acc = rb[0];
#pragma unroll
        for (int k = 0; k < 16; k++) {
            float yk_ = __shfl_sync(FULLMASK, ynew, 2 * k);
            acc = fmaf(rW[k], yk_, acc);
        }
        if (lane == 0) out[b * 2 + 1] = acc;
    }
}

extern "C" void kernel_launch(void* const* d_in, const int* in_sizes, int n_in,
                              void* d_out, int out_size) {
    const float* ts  = (const float*)d_in[0];
    const float* ys  = (const float*)d_in[1];
    const float* iW1 = (const float*)d_in[2];
    const float* ib1 = (const float*)d_in[3];
    const float* iW2 = (const float*)d_in[4];
    const float* ib2 = (const float*)d_in[5];
    const float* vW1 = (const float*)d_in[6];
    const float* vb1 = (const float*)d_in[7];
    const float* vW2 = (const float*)d_in[8];
    const float* vb2 = (const float*)d_in[9];
    const float* cW1 = (const float*)d_in[10];
    const float* cb1 = (const float*)d_in[11];
    const float* cW2 = (const float*)d_in[12];
    const float* cb2 = (const float*)d_in[13];
    const float* rW  = (const float*)d_in[14];
    const float* rb  = (const float*)d_in[15];

    const int Bn = out_size / 2;  // (B, 2, 1) float32
    sde_scan_kernel<<<Bn, 32>>>(ts, ys, iW1, ib1, iW2, ib2,
                                vW1, vb1, vW2, vb2,
                                cW1, cb1, cW2, cb2, rW, rb,
                                (float*)d_out);
}